// round 3
// baseline (speedup 1.0000x reference)
#include <cuda_runtime.h>
#include <math.h>

#define HID   16
#define NPIX  131072            // B*H*W = 2*256*256
#define HW    65536
#define EPSF  1e-6f

// ---------------- scratch (static __device__, no allocation) ----------------
// NHWC, 16 channels = 4x float4 per pixel
__device__ float4 g4_short[NPIX * 4];
__device__ float4 g4_feat0[NPIX * 4];
__device__ float4 g4_n1[NPIX * 4];
__device__ float4 g4_a1[NPIX * 4];
__device__ float4 g4_feat[NPIX * 4];
__device__ float4 g_sig[NPIX];             // (sx, sy, sr, -)

// ---------------- weights in constant memory ----------------
__constant__ float c_pm_w[16], c_pm_b[16], c_pa_w[48], c_pa_b[16], c_n1w[16];
__constant__ float c_fdw_w[144], c_fdw_b[16], c_fpw_w[1200], c_fpw_b[75];
__constant__ float c_cdw_w[144], c_cdw_b[16], c_cpw_w[1200], c_cpw_b[75];
__constant__ float c_n2w[16], c_gate_w[256], c_gate_b[16], c_pout_w[256], c_pout_b[16];
__constant__ float c_sig_w[48], c_sig_b[3], c_off_w[800], c_off_b[50];

// ---------------- float4 helpers ----------------
__device__ __forceinline__ float4 f4fma(float a, float4 b, float4 c) {
    return make_float4(fmaf(a, b.x, c.x), fmaf(a, b.y, c.y),
                       fmaf(a, b.z, c.z), fmaf(a, b.w, c.w));
}
__device__ __forceinline__ float4 f4scale(float a, float4 b) {
    return make_float4(a * b.x, a * b.y, a * b.z, a * b.w);
}
__device__ __forceinline__ float dot4c(float4 a, const float* w) {
    return fmaf(a.x, w[0], fmaf(a.y, w[1], fmaf(a.z, w[2], a.w * w[3])));
}
// sum across the 4 lanes of a pixel group (lanes aligned to 4)
__device__ __forceinline__ float rsum4(float v) {
    v += __shfl_xor_sync(0xffffffffu, v, 1);
    v += __shfl_xor_sync(0xffffffffu, v, 2);
    return v;
}

// ---------------- scalar helpers ----------------
__device__ __forceinline__ float geluf(float v) {
    return 0.5f * v * (1.0f + erff(v * 0.7071067811865476f));
}
__device__ __forceinline__ float tanh_p(float x) {
    float ax = fabsf(x);
    float e = __expf(2.0f * ax);       // inf for large -> t = 1
    float t = 1.0f - 2.0f / (e + 1.0f);
    return copysignf(t, x);
}
__device__ __forceinline__ float reflectf(float c) {
    c = fmodf(fabsf(c), 510.0f);
    return c > 255.0f ? 510.0f - c : c;
}
__device__ __forceinline__ int reflecti(int i) {
    i = abs(i);
    return i > 255 ? 510 - i : i;
}

struct Tap { int i00, i01, i10, i11; float w00, w01, w10, w11; };

__device__ __forceinline__ Tap mk_tap(float ix, float iy) {
    ix = reflectf(ix);
    iy = reflectf(iy);
    float fx = floorf(ix), fy = floorf(iy);
    float wx = ix - fx, wy = iy - fy;
    int x0 = (int)fx, y0 = (int)fy;
    int x1 = min(x0 + 1, 255), y1 = min(y0 + 1, 255);
    Tap t;
    t.i00 = (y0 << 8) + x0;  t.i01 = (y0 << 8) + x1;
    t.i10 = (y1 << 8) + x0;  t.i11 = (y1 << 8) + x1;
    float omx = 1.0f - wx, omy = 1.0f - wy;
    t.w00 = omx * omy;  t.w01 = wx * omy;
    t.w10 = omx * wy;   t.w11 = wx * wy;
    return t;
}

// broadcast full 16-ch vector from the 4 lanes' chunks
__device__ __forceinline__ void bcast16(float4 v, int lane, float out[16]) {
    int base = lane & ~3;
#pragma unroll
    for (int q = 0; q < 4; q++) {
        out[4 * q + 0] = __shfl_sync(0xffffffffu, v.x, base + q);
        out[4 * q + 1] = __shfl_sync(0xffffffffu, v.y, base + q);
        out[4 * q + 2] = __shfl_sync(0xffffffffu, v.z, base + q);
        out[4 * q + 3] = __shfl_sync(0xffffffffu, v.w, base + q);
    }
}

// ---------------- K1: proj + gelu + rmsnorm (4 lanes / pixel) ----------------
__global__ void k1_proj(const float* __restrict__ x) {
    int t = blockIdx.x * blockDim.x + threadIdx.x;
    int p = t >> 2, j = t & 3;
    int b = p >> 16;
    int hw = p & 0xFFFF;
    const float* xb = x + (size_t)b * 4 * HW;
    float x0 = xb[hw], x1 = xb[HW + hw], x2 = xb[2 * HW + hw], x3 = xb[3 * HW + hw];

    int c0 = 4 * j;
    float sc[4], f0[4];
    float ssp = 0.0f;
#pragma unroll
    for (int q = 0; q < 4; q++) {
        int c = c0 + q;
        float v = c_pm_w[c] * x0 + c_pm_b[c] + c_pa_b[c]
                + c_pa_w[c * 3 + 0] * x1 + c_pa_w[c * 3 + 1] * x2 + c_pa_w[c * 3 + 2] * x3;
        sc[q] = v;
        float g = geluf(v);
        f0[q] = g;
        ssp += g * g;
    }
    float ss = rsum4(ssp);
    float inv = 1.0f / (sqrtf(ss) * 0.25f + EPSF);

    g4_short[(size_t)p * 4 + j] = make_float4(sc[0], sc[1], sc[2], sc[3]);
    g4_feat0[(size_t)p * 4 + j] = make_float4(f0[0], f0[1], f0[2], f0[3]);
    g4_n1[(size_t)p * 4 + j] = make_float4(f0[0] * inv * c_n1w[c0],
                                           f0[1] * inv * c_n1w[c0 + 1],
                                           f0[2] * inv * c_n1w[c0 + 2],
                                           f0[3] * inv * c_n1w[c0 + 3]);
}

// ---------------- deform core, lane-split (M=0 fine, M=1 coarse) ----------------
// Returns this lane's 4-channel chunk of the output.
template <int M>
__device__ __forceinline__ float4 deform_core4(const float4* __restrict__ sb,
                                               int y, int x, int j) {
    const float SPACING = (M == 0) ? 1.0f : 3.0f;
    const float MO      = (M == 0) ? 4.0f : 6.0f;
    const float* dwb = (M == 0) ? c_fdw_b : c_cdw_b;
    const float* dww = (M == 0) ? c_fdw_w : c_cdw_w;
    const float* pwb = (M == 0) ? c_fpw_b : c_cpw_b;
    const float* pww = (M == 0) ? c_fpw_w : c_cpw_w;
    const int c0 = 4 * j;

    // depthwise 3x3 (reflect) + bias -- lane handles its 4 channels
    float4 h = make_float4(dwb[c0], dwb[c0 + 1], dwb[c0 + 2], dwb[c0 + 3]);
#pragma unroll
    for (int ky = 0; ky < 3; ky++) {
        int yy = reflecti(y + ky - 1);
#pragma unroll
        for (int kx = 0; kx < 3; kx++) {
            int xx = reflecti(x + kx - 1);
            float4 v = sb[(((yy << 8) + xx) << 2) + j];
            const float* wb = dww + ky * 3 + kx;
            h.x = fmaf(v.x, wb[(c0 + 0) * 9], h.x);
            h.y = fmaf(v.y, wb[(c0 + 1) * 9], h.y);
            h.z = fmaf(v.z, wb[(c0 + 2) * 9], h.z);
            h.w = fmaf(v.w, wb[(c0 + 3) * 9], h.w);
        }
    }
    h.x = geluf(h.x); h.y = geluf(h.y); h.z = geluf(h.z); h.w = geluf(h.w);

    // fused pw-conv + softmax-weighted sampling
    float4 acc = make_float4(0.f, 0.f, 0.f, 0.f);
    float den = 0.0f;

#pragma unroll 1
    for (int k = 0; k < 25; k++) {
        float pxp = dot4c(h, pww + (2 * k) * 16 + c0);
        float pyp = dot4c(h, pww + (2 * k + 1) * 16 + c0);
        float plp = dot4c(h, pww + (50 + k) * 16 + c0);
        float px = rsum4(pxp) + pwb[2 * k];
        float py = rsum4(pyp) + pwb[2 * k + 1];
        float pl = rsum4(plp) + pwb[50 + k];

        float dx = SPACING * (float)((k % 5) - 2) + tanh_p(px) * MO;
        float dy = SPACING * (float)((k / 5) - 2) + tanh_p(py) * MO;
        float e = __expf(pl);
        Tap t = mk_tap((float)x + dx, (float)y + dy);

        float4 s = f4scale(t.w00, sb[(t.i00 << 2) + j]);
        s = f4fma(t.w01, sb[(t.i01 << 2) + j], s);
        s = f4fma(t.w10, sb[(t.i10 << 2) + j], s);
        s = f4fma(t.w11, sb[(t.i11 << 2) + j], s);
        acc = f4fma(e, s, acc);
        den += e;
    }
    return f4scale(1.0f / den, acc);
}

// ---------------- K2: fine deform  (n1 -> a1) ----------------
__global__ void k2_fine() {
    int t = blockIdx.x * blockDim.x + threadIdx.x;
    int p = t >> 2, j = t & 3;
    int b = p >> 16, y = (p >> 8) & 255, x = p & 255;
    const float4* sb = g4_n1 + ((size_t)b << 18);
    g4_a1[(size_t)p * 4 + j] = deform_core4<0>(sb, y, x, j);
}

// ---------------- K3: coarse deform + rmsnorm + gate + proj_out + sigma ----------------
__global__ void k3_coarse_tail() {
    int t = blockIdx.x * blockDim.x + threadIdx.x;
    int p = t >> 2, j = t & 3;
    int lane = threadIdx.x & 31;
    int b = p >> 16, y = (p >> 8) & 255, x = p & 255;
    const int c0 = 4 * j;
    const float4* sb = g4_a1 + ((size_t)b << 18);

    float4 av = deform_core4<1>(sb, y, x, j);

    // rmsnorm(a2, norm2)
    float ssp = av.x * av.x + av.y * av.y + av.z * av.z + av.w * av.w;
    float ss = rsum4(ssp);
    float inv = 1.0f / (sqrtf(ss) * 0.25f + EPSF);
    float4 tv = make_float4(av.x * inv * c_n2w[c0], av.y * inv * c_n2w[c0 + 1],
                            av.z * inv * c_n2w[c0 + 2], av.w * inv * c_n2w[c0 + 3]);

    // full t vector via shuffle broadcast
    float tf[16];
    bcast16(tv, lane, tf);

    // gate conv for this lane's 4 outputs, then g = feat0 * a3
    float4 f0v = g4_feat0[(size_t)p * 4 + j];
    float gq[4];
#pragma unroll
    for (int q = 0; q < 4; q++) {
        int o = c0 + q;
        float a3 = c_gate_b[o];
#pragma unroll
        for (int c = 0; c < 16; c++) a3 = fmaf(c_gate_w[o * 16 + c], tf[c], a3);
        gq[q] = ((const float*)&f0v)[q] * a3;
    }
    float4 gv = make_float4(gq[0], gq[1], gq[2], gq[3]);

    // full g vector
    float gf[16];
    bcast16(gv, lane, gf);

    // feat = proj_out(g) + b + shortcut (lane's 4 outputs)
    float4 scv = g4_short[(size_t)p * 4 + j];
    float featq[4];
#pragma unroll
    for (int q = 0; q < 4; q++) {
        int o = c0 + q;
        float v = c_pout_b[o] + ((const float*)&scv)[q];
#pragma unroll
        for (int c = 0; c < 16; c++) v = fmaf(c_pout_w[o * 16 + c], gf[c], v);
        featq[q] = v;
    }
    float4 fv = make_float4(featq[0], featq[1], featq[2], featq[3]);
    g4_feat[(size_t)p * 4 + j] = fv;

    // sigma head: min(softplus(.), 6) + eps  (partials over lane chunk)
    float sig[3];
#pragma unroll
    for (int r = 0; r < 3; r++) {
        float zp = dot4c(fv, c_sig_w + r * 16 + c0);
        float z = rsum4(zp) + c_sig_b[r];
        float sp = fmaxf(z, 0.0f) + log1pf(expf(-fabsf(z)));
        sig[r] = fminf(sp, 6.0f) + EPSF;
    }
    if (j == 0) g_sig[p] = make_float4(sig[0], sig[1], sig[2], 0.0f);
}

// ---------------- K4: joint bilateral ----------------
__global__ void k4_bilateral(const float* __restrict__ xin, float* __restrict__ out) {
    int t = blockIdx.x * blockDim.x + threadIdx.x;
    int p = t >> 2, j = t & 3;
    int b = p >> 16, y = (p >> 8) & 255, x = p & 255;
    const int c0 = 4 * j;

    float4 fv = g4_feat[(size_t)p * 4 + j];

    float4 s4 = g_sig[p];
    float axc = 0.5f / (s4.x * s4.x);
    float ayc = 0.5f / (s4.y * s4.y);
    float arc = 0.5f / (s4.z * s4.z);

    const float* plane = xin + (size_t)b * 4 * HW;          // channel 0 of batch b
    const float4* fb = g4_feat + ((size_t)b << 18);

    float num = 0.0f, den = 0.0f;
#pragma unroll 1
    for (int k = 0; k < 25; k++) {
        float pxp = dot4c(fv, c_off_w + (2 * k) * 16 + c0);
        float pyp = dot4c(fv, c_off_w + (2 * k + 1) * 16 + c0);
        float px = rsum4(pxp) + c_off_b[2 * k];
        float py = rsum4(pyp) + c_off_b[2 * k + 1];

        float dx = (float)((k % 5) - 2) + tanh_p(px) * 5.0f;
        float dy = (float)((k / 5) - 2) + tanh_p(py) * 5.0f;
        Tap tp = mk_tap((float)x + dx, (float)y + dy);

        // feat gather: this lane's chunk from all 4 corners
        float4 s = f4scale(tp.w00, fb[(tp.i00 << 2) + j]);
        s = f4fma(tp.w01, fb[(tp.i01 << 2) + j], s);
        s = f4fma(tp.w10, fb[(tp.i10 << 2) + j], s);
        s = f4fma(tp.w11, fb[(tp.i11 << 2) + j], s);
        float ddx = fv.x - s.x, ddy = fv.y - s.y, ddz = fv.z - s.z, ddw = fv.w - s.w;
        float fdp = ddx * ddx + ddy * ddy + ddz * ddz + ddw * ddw;

        // patch partial: lane j loads its corner only
        int ci = (j & 2) ? ((j & 1) ? tp.i11 : tp.i10) : ((j & 1) ? tp.i01 : tp.i00);
        float cw = (j & 2) ? ((j & 1) ? tp.w11 : tp.w10) : ((j & 1) ? tp.w01 : tp.w00);
        float pp = cw * plane[ci];

        float fd = rsum4(fdp);
        float patch = rsum4(pp);

        float w = __expf(-(dx * dx * axc + dy * dy * ayc) - fd * arc);
        num = fmaf(patch, w, num);
        den += w;
    }
    if (j == 0) out[p] = num / (den + 1e-8f);
}

// ---------------- launch ----------------
extern "C" void kernel_launch(void* const* d_in, const int* in_sizes, int n_in,
                              void* d_out, int out_size) {
    const float* x = (const float*)d_in[0];

#define CPY(sym, idx, n) cudaMemcpyToSymbolAsync(sym, d_in[idx], (n) * sizeof(float), 0, \
                                                 cudaMemcpyDeviceToDevice, 0)
    CPY(c_pm_w,   1, 16);   CPY(c_pm_b,   2, 16);
    CPY(c_pa_w,   3, 48);   CPY(c_pa_b,   4, 16);
    CPY(c_n1w,    5, 16);
    CPY(c_fdw_w,  6, 144);  CPY(c_fdw_b,  7, 16);
    CPY(c_fpw_w,  8, 1200); CPY(c_fpw_b,  9, 75);
    CPY(c_cdw_w, 10, 144);  CPY(c_cdw_b, 11, 16);
    CPY(c_cpw_w, 12, 1200); CPY(c_cpw_b, 13, 75);
    CPY(c_n2w,   14, 16);
    CPY(c_gate_w,15, 256);  CPY(c_gate_b,16, 16);
    CPY(c_pout_w,17, 256);  CPY(c_pout_b,18, 16);
    CPY(c_sig_w, 19, 48);   CPY(c_sig_b, 20, 3);
    CPY(c_off_w, 21, 800);  CPY(c_off_b, 22, 50);
#undef CPY

    const int TB = 128;
    const int NB4 = (NPIX * 4) / TB;   // 4 lanes per pixel
    k1_proj<<<NB4, TB>>>(x);
    k2_fine<<<NB4, TB>>>();
    k3_coarse_tail<<<NB4, TB>>>();
    k4_bilateral<<<NB4, TB>>>(x, (float*)d_out);
}

// round 4
// speedup vs baseline: 1.9890x; 1.9890x over previous
#include <cuda_runtime.h>
#include <math.h>

#define NPIX  131072            // B*H*W = 2*256*256
#define HW    65536
#define EPSF  1e-6f

// ---------------- scratch (static __device__, no allocation) ----------------
__device__ float4 g4_short[NPIX * 4];
__device__ float4 g4_feat0[NPIX * 4];
__device__ float4 g4_n1[NPIX * 4];
__device__ float4 g4_a1[NPIX * 4];
__device__ float4 g4_feat[NPIX * 4];
__device__ float4 g_sig[NPIX];             // (sx, sy, sr, -)

// ---------------- helpers ----------------
__device__ __forceinline__ float4 f4fma(float a, float4 b, float4 c) {
    return make_float4(fmaf(a, b.x, c.x), fmaf(a, b.y, c.y),
                       fmaf(a, b.z, c.z), fmaf(a, b.w, c.w));
}
__device__ __forceinline__ float4 f4scale(float a, float4 b) {
    return make_float4(a * b.x, a * b.y, a * b.z, a * b.w);
}
__device__ __forceinline__ float dot44(float4 a, float4 b) {
    return fmaf(a.x, b.x, fmaf(a.y, b.y, fmaf(a.z, b.z, a.w * b.w)));
}
__device__ __forceinline__ float rsum4(float v) {
    v += __shfl_xor_sync(0xffffffffu, v, 1);
    v += __shfl_xor_sync(0xffffffffu, v, 2);
    return v;
}
// broadcast full 16-ch vector (as 4x float4) from the 4 lanes' chunks
__device__ __forceinline__ void bcast16v(float4 v, int lane, float4 out[4]) {
    int base = lane & ~3;
#pragma unroll
    for (int q = 0; q < 4; q++) {
        out[q] = make_float4(__shfl_sync(0xffffffffu, v.x, base + q),
                             __shfl_sync(0xffffffffu, v.y, base + q),
                             __shfl_sync(0xffffffffu, v.z, base + q),
                             __shfl_sync(0xffffffffu, v.w, base + q));
    }
}
__device__ __forceinline__ float geluf(float v) {
    return 0.5f * v * (1.0f + erff(v * 0.7071067811865476f));
}
__device__ __forceinline__ float tanh_p(float x) {
    float ax = fabsf(x);
    float e = __expf(2.0f * ax);
    float t = 1.0f - 2.0f / (e + 1.0f);
    return copysignf(t, x);
}
__device__ __forceinline__ float reflectf(float c) {
    c = fmodf(fabsf(c), 510.0f);
    return c > 255.0f ? 510.0f - c : c;
}
__device__ __forceinline__ int reflecti(int i) {
    i = abs(i);
    return i > 255 ? 510 - i : i;
}

// ---------------- K1: proj + gelu + rmsnorm (4 lanes / pixel) ----------------
__global__ void k1_proj(const float* __restrict__ x,
                        const float* __restrict__ pm_w, const float* __restrict__ pm_b,
                        const float* __restrict__ pa_w, const float* __restrict__ pa_b,
                        const float* __restrict__ n1w) {
    int t = blockIdx.x * blockDim.x + threadIdx.x;
    int p = t >> 2, j = t & 3;
    int b = p >> 16;
    int hw = p & 0xFFFF;
    const float* xb = x + (size_t)b * 4 * HW;
    float x0 = xb[hw], x1 = xb[HW + hw], x2 = xb[2 * HW + hw], x3 = xb[3 * HW + hw];

    int c0 = 4 * j;
    float sc[4], f0[4];
    float ssp = 0.0f;
#pragma unroll
    for (int q = 0; q < 4; q++) {
        int c = c0 + q;
        float v = pm_w[c] * x0 + pm_b[c] + pa_b[c]
                + pa_w[c * 3 + 0] * x1 + pa_w[c * 3 + 1] * x2 + pa_w[c * 3 + 2] * x3;
        sc[q] = v;
        float g = geluf(v);
        f0[q] = g;
        ssp += g * g;
    }
    float ss = rsum4(ssp);
    float inv = 1.0f / (sqrtf(ss) * 0.25f + EPSF);

    g4_short[(size_t)p * 4 + j] = make_float4(sc[0], sc[1], sc[2], sc[3]);
    g4_feat0[(size_t)p * 4 + j] = make_float4(f0[0], f0[1], f0[2], f0[3]);
    g4_n1[(size_t)p * 4 + j] = make_float4(f0[0] * inv * n1w[c0],
                                           f0[1] * inv * n1w[c0 + 1],
                                           f0[2] * inv * n1w[c0 + 2],
                                           f0[3] * inv * n1w[c0 + 3]);
}

// ---------------- deform core: hybrid k-split / channel-split ----------------
// tap_s: per-pixel-group smem, 25 slots of (ix_refl, iy_refl, e, -)
__device__ __forceinline__ float4 deform_core4(
    const float4* __restrict__ sb, int y, int x, int lane, int j,
    const float* __restrict__ dww, const float* __restrict__ dwb,
    const float* __restrict__ pww, const float* __restrict__ pwb,
    float spacing, float mo, float4* tap_s)
{
    const int c0 = 4 * j;

    // depthwise 3x3 (reflect) + bias, channel-split
    float4 h = make_float4(dwb[c0], dwb[c0 + 1], dwb[c0 + 2], dwb[c0 + 3]);
#pragma unroll
    for (int ky = 0; ky < 3; ky++) {
        int yy = reflecti(y + ky - 1);
#pragma unroll
        for (int kx = 0; kx < 3; kx++) {
            int xx = reflecti(x + kx - 1);
            float4 v = sb[(((yy << 8) + xx) << 2) + j];
            const float* wb = dww + ky * 3 + kx;
            h.x = fmaf(v.x, wb[(c0 + 0) * 9], h.x);
            h.y = fmaf(v.y, wb[(c0 + 1) * 9], h.y);
            h.z = fmaf(v.z, wb[(c0 + 2) * 9], h.z);
            h.w = fmaf(v.w, wb[(c0 + 3) * 9], h.w);
        }
    }
    h.x = geluf(h.x); h.y = geluf(h.y); h.z = geluf(h.z); h.w = geluf(h.w);

    // full h vector to all lanes
    float4 hv[4];
    bcast16v(h, lane, hv);

    // phase 1: lane j owns k = j, j+4, ... computes full dots + transcendentals
    const float4* pww4 = (const float4*)pww;
    for (int k = j; k < 25; k += 4) {
        const float4* wx4 = pww4 + (2 * k) * 4;
        const float4* wy4 = pww4 + (2 * k + 1) * 4;
        const float4* wl4 = pww4 + (50 + k) * 4;
        float px = pwb[2 * k], py = pwb[2 * k + 1], pl = pwb[50 + k];
#pragma unroll
        for (int q = 0; q < 4; q++) {
            px = fmaf(dot44(hv[q], wx4[q]), 1.0f, px);
            py += dot44(hv[q], wy4[q]);
            pl += dot44(hv[q], wl4[q]);
        }
        float dx = spacing * (float)((k % 5) - 2) + tanh_p(px) * mo;
        float dy = spacing * (float)((k / 5) - 2) + tanh_p(py) * mo;
        tap_s[k] = make_float4(reflectf((float)x + dx), reflectf((float)y + dy),
                               __expf(pl), 0.0f);
    }
    __syncwarp();

    // phase 2: channel-split gather over all 25 taps
    float4 acc = make_float4(0.f, 0.f, 0.f, 0.f);
    float den = 0.0f;
#pragma unroll 1
    for (int k = 0; k < 25; k++) {
        float4 tp = tap_s[k];
        float fx = floorf(tp.x), fy = floorf(tp.y);
        float wx = tp.x - fx, wy = tp.y - fy;
        int x0 = (int)fx, y0 = (int)fy;
        int x1 = min(x0 + 1, 255), y1 = min(y0 + 1, 255);
        int r0 = y0 << 8, r1 = y1 << 8;
        float omx = 1.0f - wx, omy = 1.0f - wy;
        float4 s = f4scale(omx * omy, sb[((r0 + x0) << 2) + j]);
        s = f4fma(wx * omy, sb[((r0 + x1) << 2) + j], s);
        s = f4fma(omx * wy, sb[((r1 + x0) << 2) + j], s);
        s = f4fma(wx * wy, sb[((r1 + x1) << 2) + j], s);
        acc = f4fma(tp.z, s, acc);
        den += tp.z;
    }
    __syncwarp();
    return f4scale(1.0f / den, acc);
}

// ---------------- K2: fine deform  (n1 -> a1) ----------------
__global__ void k2_fine(const float* __restrict__ dww, const float* __restrict__ dwb,
                        const float* __restrict__ pww, const float* __restrict__ pwb) {
    __shared__ float4 s_tap[32][25];
    int t = blockIdx.x * blockDim.x + threadIdx.x;
    int p = t >> 2, j = t & 3;
    int lane = threadIdx.x & 31;
    int g = threadIdx.x >> 2;
    int b = p >> 16, y = (p >> 8) & 255, x = p & 255;
    const float4* sb = g4_n1 + ((size_t)b << 18);
    g4_a1[(size_t)p * 4 + j] =
        deform_core4(sb, y, x, lane, j, dww, dwb, pww, pwb, 1.0f, 4.0f, &s_tap[g][0]);
}

// ---------------- K3: coarse deform + rmsnorm + gate + proj_out + sigma ----------------
__global__ void k3_coarse_tail(
    const float* __restrict__ dww, const float* __restrict__ dwb,
    const float* __restrict__ pww, const float* __restrict__ pwb,
    const float* __restrict__ n2w,
    const float* __restrict__ gate_w, const float* __restrict__ gate_b,
    const float* __restrict__ pout_w, const float* __restrict__ pout_b,
    const float* __restrict__ sig_w, const float* __restrict__ sig_b) {
    __shared__ float4 s_tap[32][25];
    int t = blockIdx.x * blockDim.x + threadIdx.x;
    int p = t >> 2, j = t & 3;
    int lane = threadIdx.x & 31;
    int g = threadIdx.x >> 2;
    int b = p >> 16, y = (p >> 8) & 255, x = p & 255;
    const int c0 = 4 * j;
    const float4* sb = g4_a1 + ((size_t)b << 18);

    float4 av = deform_core4(sb, y, x, lane, j, dww, dwb, pww, pwb, 3.0f, 6.0f, &s_tap[g][0]);

    // rmsnorm(a2, norm2)
    float ssp = av.x * av.x + av.y * av.y + av.z * av.z + av.w * av.w;
    float ss = rsum4(ssp);
    float inv = 1.0f / (sqrtf(ss) * 0.25f + EPSF);
    float4 tv = make_float4(av.x * inv * n2w[c0], av.y * inv * n2w[c0 + 1],
                            av.z * inv * n2w[c0 + 2], av.w * inv * n2w[c0 + 3]);

    float4 tf[4];
    bcast16v(tv, lane, tf);

    // gate conv (this lane's 4 outputs), then g = feat0 * a3
    const float4* gate4 = (const float4*)gate_w;
    float4 f0v = g4_feat0[(size_t)p * 4 + j];
    float gq[4];
#pragma unroll
    for (int q = 0; q < 4; q++) {
        int o = c0 + q;
        float a3 = gate_b[o];
#pragma unroll
        for (int r = 0; r < 4; r++) a3 += dot44(gate4[o * 4 + r], tf[r]);
        gq[q] = ((const float*)&f0v)[q] * a3;
    }
    float4 gv = make_float4(gq[0], gq[1], gq[2], gq[3]);

    float4 gf[4];
    bcast16v(gv, lane, gf);

    // feat = proj_out(g) + b + shortcut (lane's 4 outputs)
    const float4* pout4 = (const float4*)pout_w;
    float4 scv = g4_short[(size_t)p * 4 + j];
    float featq[4];
#pragma unroll
    for (int q = 0; q < 4; q++) {
        int o = c0 + q;
        float v = pout_b[o] + ((const float*)&scv)[q];
#pragma unroll
        for (int r = 0; r < 4; r++) v += dot44(pout4[o * 4 + r], gf[r]);
        featq[q] = v;
    }
    float4 fv = make_float4(featq[0], featq[1], featq[2], featq[3]);
    g4_feat[(size_t)p * 4 + j] = fv;

    // sigma head
    const float4* sig4 = (const float4*)sig_w;
    float sg[3];
#pragma unroll
    for (int r = 0; r < 3; r++) {
        float zp = dot44(fv, sig4[r * 4 + j]);
        float z = rsum4(zp) + sig_b[r];
        float sp = fmaxf(z, 0.0f) + log1pf(expf(-fabsf(z)));
        sg[r] = fminf(sp, 6.0f) + EPSF;
    }
    if (j == 0) g_sig[p] = make_float4(sg[0], sg[1], sg[2], 0.0f);
}

// ---------------- K4: joint bilateral ----------------
__global__ void k4_bilateral(const float* __restrict__ xin,
                             const float* __restrict__ offw, const float* __restrict__ offb,
                             float* __restrict__ out) {
    __shared__ float4 s_tap[32][25];
    int t = blockIdx.x * blockDim.x + threadIdx.x;
    int p = t >> 2, j = t & 3;
    int lane = threadIdx.x & 31;
    int g = threadIdx.x >> 2;
    int b = p >> 16, y = (p >> 8) & 255, x = p & 255;

    float4 fv = g4_feat[(size_t)p * 4 + j];
    float4 fvv[4];
    bcast16v(fv, lane, fvv);

    float4 s4 = g_sig[p];
    float axc = 0.5f / (s4.x * s4.x);
    float ayc = 0.5f / (s4.y * s4.y);
    float arc = 0.5f / (s4.z * s4.z);

    const float* plane = xin + (size_t)b * 4 * HW;
    const float4* fb = g4_feat + ((size_t)b << 18);
    const float4* offw4 = (const float4*)offw;
    float4* tap_s = &s_tap[g][0];

    // phase 1: lane j owns k = j, j+4, ...
    for (int k = j; k < 25; k += 4) {
        const float4* wx4 = offw4 + (2 * k) * 4;
        const float4* wy4 = offw4 + (2 * k + 1) * 4;
        float px = offb[2 * k], py = offb[2 * k + 1];
#pragma unroll
        for (int q = 0; q < 4; q++) {
            px += dot44(fvv[q], wx4[q]);
            py += dot44(fvv[q], wy4[q]);
        }
        float dx = (float)((k % 5) - 2) + tanh_p(px) * 5.0f;
        float dy = (float)((k / 5) - 2) + tanh_p(py) * 5.0f;
        float spat = dx * dx * axc + dy * dy * ayc;
        tap_s[k] = make_float4(reflectf((float)x + dx), reflectf((float)y + dy), spat, 0.0f);
    }
    __syncwarp();

    // phase 2
    float num = 0.0f, den = 0.0f;
#pragma unroll 1
    for (int k = 0; k < 25; k++) {
        float4 tp = tap_s[k];
        float fx = floorf(tp.x), fy = floorf(tp.y);
        float wx = tp.x - fx, wy = tp.y - fy;
        int x0 = (int)fx, y0 = (int)fy;
        int x1 = min(x0 + 1, 255), y1 = min(y0 + 1, 255);
        int r0 = y0 << 8, r1 = y1 << 8;
        int i00 = r0 + x0, i01 = r0 + x1, i10 = r1 + x0, i11 = r1 + x1;
        float omx = 1.0f - wx, omy = 1.0f - wy;
        float w00 = omx * omy, w01 = wx * omy, w10 = omx * wy, w11 = wx * wy;

        // feat gather: this lane's chunk from all 4 corners
        float4 s = f4scale(w00, fb[(i00 << 2) + j]);
        s = f4fma(w01, fb[(i01 << 2) + j], s);
        s = f4fma(w10, fb[(i10 << 2) + j], s);
        s = f4fma(w11, fb[(i11 << 2) + j], s);
        float ddx = fv.x - s.x, ddy = fv.y - s.y, ddz = fv.z - s.z, ddw = fv.w - s.w;
        float fdp = ddx * ddx + ddy * ddy + ddz * ddz + ddw * ddw;

        // patch partial: lane j loads its corner only
        int ci = (j & 2) ? ((j & 1) ? i11 : i10) : ((j & 1) ? i01 : i00);
        float cw = (j & 2) ? ((j & 1) ? w11 : w10) : ((j & 1) ? w01 : w00);
        float pp = cw * plane[ci];

        float fd = rsum4(fdp);
        float patch = rsum4(pp);

        float w = __expf(-tp.z - fd * arc);
        num = fmaf(patch, w, num);
        den += w;
    }
    if (j == 0) out[p] = num / (den + 1e-8f);
}

// ---------------- launch ----------------
extern "C" void kernel_launch(void* const* d_in, const int* in_sizes, int n_in,
                              void* d_out, int out_size) {
    const float* x = (const float*)d_in[0];
    const int TB = 128;
    const int NB4 = (NPIX * 4) / TB;   // 4 lanes per pixel

    k1_proj<<<NB4, TB>>>(x, (const float*)d_in[1], (const float*)d_in[2],
                         (const float*)d_in[3], (const float*)d_in[4],
                         (const float*)d_in[5]);
    k2_fine<<<NB4, TB>>>((const float*)d_in[6], (const float*)d_in[7],
                         (const float*)d_in[8], (const float*)d_in[9]);
    k3_coarse_tail<<<NB4, TB>>>((const float*)d_in[10], (const float*)d_in[11],
                                (const float*)d_in[12], (const float*)d_in[13],
                                (const float*)d_in[14],
                                (const float*)d_in[15], (const float*)d_in[16],
                                (const float*)d_in[17], (const float*)d_in[18],
                                (const float*)d_in[19], (const float*)d_in[20]);
    k4_bilateral<<<NB4, TB>>>(x, (const float*)d_in[21], (const float*)d_in[22],
                              (float*)d_out);
}

// round 5
// speedup vs baseline: 2.8094x; 1.4124x over previous
#include <cuda_runtime.h>
#include <math.h>

#define NPIX  131072            // B*H*W = 2*256*256
#define HW    65536
#define EPSF  1e-6f

// ---------------- scratch (static __device__, no allocation) ----------------
__device__ float4 g4_short[NPIX * 4];
__device__ float4 g4_feat0[NPIX * 4];
__device__ float4 g4_n1[NPIX * 4];
__device__ float4 g4_a1[NPIX * 4];
__device__ float4 g4_feat[NPIX * 4];
__device__ float4 g_sig[NPIX];             // (sx, sy, sr, -)

// ---------------- helpers ----------------
__device__ __forceinline__ float4 f4fma(float a, float4 b, float4 c) {
    return make_float4(fmaf(a, b.x, c.x), fmaf(a, b.y, c.y),
                       fmaf(a, b.z, c.z), fmaf(a, b.w, c.w));
}
__device__ __forceinline__ float4 f4scale(float a, float4 b) {
    return make_float4(a * b.x, a * b.y, a * b.z, a * b.w);
}
__device__ __forceinline__ float4 f4add(float4 a, float4 b) {
    return make_float4(a.x + b.x, a.y + b.y, a.z + b.z, a.w + b.w);
}
__device__ __forceinline__ float dot44(float4 a, float4 b) {
    return fmaf(a.x, b.x, fmaf(a.y, b.y, fmaf(a.z, b.z, a.w * b.w)));
}
__device__ __forceinline__ float rsum4(float v) {
    v += __shfl_xor_sync(0xffffffffu, v, 1);
    v += __shfl_xor_sync(0xffffffffu, v, 2);
    return v;
}
// broadcast full 16-ch vector (as 4x float4) from the 4 lanes' chunks
__device__ __forceinline__ void bcast16v(float4 v, int lane, float4 out[4]) {
    int base = lane & ~3;
#pragma unroll
    for (int q = 0; q < 4; q++) {
        out[q] = make_float4(__shfl_sync(0xffffffffu, v.x, base + q),
                             __shfl_sync(0xffffffffu, v.y, base + q),
                             __shfl_sync(0xffffffffu, v.z, base + q),
                             __shfl_sync(0xffffffffu, v.w, base + q));
    }
}
__device__ __forceinline__ float geluf(float v) {
    return 0.5f * v * (1.0f + erff(v * 0.7071067811865476f));
}
__device__ __forceinline__ float tanh_p(float x) {
    float ax = fabsf(x);
    float e = __expf(2.0f * ax);
    float t = 1.0f - 2.0f / (e + 1.0f);
    return copysignf(t, x);
}
__device__ __forceinline__ float reflectf(float c) {
    c = fmodf(fabsf(c), 510.0f);
    return c > 255.0f ? 510.0f - c : c;
}
__device__ __forceinline__ int reflecti(int i) {
    i = abs(i);
    return i > 255 ? 510 - i : i;
}

// ---------------- smem loaders ----------------
__device__ __forceinline__ void ldblk(float* dst, const float* src, int n, int tid) {
    for (int i = tid; i < n; i += 128) dst[i] = src[i];
}
// pad rows 16 -> 20 floats
__device__ __forceinline__ void ldpad(float* dst, const float* src, int rows, int tid) {
    for (int i = tid; i < rows * 16; i += 128) {
        int r = i >> 4, c = i & 15;
        dst[r * 20 + c] = src[i];
    }
}
// transpose 16x16 + pad rows to 20: dst[c*20+o] = src[o*16+c]
__device__ __forceinline__ void ldtpad(float* dst, const float* src, int tid) {
    for (int i = tid; i < 256; i += 128) {
        int o = i >> 4, c = i & 15;
        dst[c * 20 + o] = src[i];
    }
}

// ---------------- K1: proj + gelu + rmsnorm (4 lanes / pixel) ----------------
__global__ void k1_proj(const float* __restrict__ x,
                        const float* __restrict__ pm_w, const float* __restrict__ pm_b,
                        const float* __restrict__ pa_w, const float* __restrict__ pa_b,
                        const float* __restrict__ n1w) {
    int t = blockIdx.x * blockDim.x + threadIdx.x;
    int p = t >> 2, j = t & 3;
    int b = p >> 16;
    int hw = p & 0xFFFF;
    const float* xb = x + (size_t)b * 4 * HW;
    float x0 = xb[hw], x1 = xb[HW + hw], x2 = xb[2 * HW + hw], x3 = xb[3 * HW + hw];

    int c0 = 4 * j;
    float sc[4], f0[4];
    float ssp = 0.0f;
#pragma unroll
    for (int q = 0; q < 4; q++) {
        int c = c0 + q;
        float v = pm_w[c] * x0 + pm_b[c] + pa_b[c]
                + pa_w[c * 3 + 0] * x1 + pa_w[c * 3 + 1] * x2 + pa_w[c * 3 + 2] * x3;
        sc[q] = v;
        float g = geluf(v);
        f0[q] = g;
        ssp += g * g;
    }
    float ss = rsum4(ssp);
    float inv = 1.0f / (sqrtf(ss) * 0.25f + EPSF);

    g4_short[(size_t)p * 4 + j] = make_float4(sc[0], sc[1], sc[2], sc[3]);
    g4_feat0[(size_t)p * 4 + j] = make_float4(f0[0], f0[1], f0[2], f0[3]);
    g4_n1[(size_t)p * 4 + j] = make_float4(f0[0] * inv * n1w[c0],
                                           f0[1] * inv * n1w[c0 + 1],
                                           f0[2] * inv * n1w[c0 + 2],
                                           f0[3] * inv * n1w[c0 + 3]);
}

// ---------------- deform core: hybrid k-split / channel-split, smem weights ----
// s_pw4: padded rows [75][5] float4; s_dww[144], s_dwb[16], s_pwb[75] in smem.
__device__ __forceinline__ float4 deform_core4(
    const float4* __restrict__ sb, int y, int x, int lane, int j,
    const float* s_dww, const float* s_dwb,
    const float4* s_pw4, const float* s_pwb,
    float spacing, float mo, float4* tap_s)
{
    const int c0 = 4 * j;

    // depthwise 3x3 (reflect) + bias, channel-split
    float4 h = make_float4(s_dwb[c0], s_dwb[c0 + 1], s_dwb[c0 + 2], s_dwb[c0 + 3]);
#pragma unroll
    for (int ky = 0; ky < 3; ky++) {
        int yy = reflecti(y + ky - 1);
#pragma unroll
        for (int kx = 0; kx < 3; kx++) {
            int xx = reflecti(x + kx - 1);
            float4 v = sb[(((yy << 8) + xx) << 2) + j];
            const float* wb = s_dww + ky * 3 + kx;
            h.x = fmaf(v.x, wb[(c0 + 0) * 9], h.x);
            h.y = fmaf(v.y, wb[(c0 + 1) * 9], h.y);
            h.z = fmaf(v.z, wb[(c0 + 2) * 9], h.z);
            h.w = fmaf(v.w, wb[(c0 + 3) * 9], h.w);
        }
    }
    h.x = geluf(h.x); h.y = geluf(h.y); h.z = geluf(h.z); h.w = geluf(h.w);

    // full h vector to all lanes
    float4 hv[4];
    bcast16v(h, lane, hv);

    // phase 1: lane j owns k = j, j+4, ...
    for (int k = j; k < 25; k += 4) {
        const float4* wx4 = s_pw4 + (2 * k) * 5;
        const float4* wy4 = s_pw4 + (2 * k + 1) * 5;
        const float4* wl4 = s_pw4 + (50 + k) * 5;
        float px = s_pwb[2 * k], py = s_pwb[2 * k + 1], pl = s_pwb[50 + k];
#pragma unroll
        for (int q = 0; q < 4; q++) {
            px += dot44(hv[q], wx4[q]);
            py += dot44(hv[q], wy4[q]);
            pl += dot44(hv[q], wl4[q]);
        }
        float dx = spacing * (float)((k % 5) - 2) + tanh_p(px) * mo;
        float dy = spacing * (float)((k / 5) - 2) + tanh_p(py) * mo;
        tap_s[k] = make_float4(reflectf((float)x + dx), reflectf((float)y + dy),
                               __expf(pl), 0.0f);
    }
    __syncwarp();

    // phase 2: channel-split gather over all 25 taps
    float4 acc = make_float4(0.f, 0.f, 0.f, 0.f);
    float den = 0.0f;
#pragma unroll 1
    for (int k = 0; k < 25; k++) {
        float4 tp = tap_s[k];
        float fx = floorf(tp.x), fy = floorf(tp.y);
        float wx = tp.x - fx, wy = tp.y - fy;
        int x0 = (int)fx, y0 = (int)fy;
        int x1 = min(x0 + 1, 255), y1 = min(y0 + 1, 255);
        int r0 = y0 << 8, r1 = y1 << 8;
        float omx = 1.0f - wx, omy = 1.0f - wy;
        float4 s = f4scale(omx * omy, sb[((r0 + x0) << 2) + j]);
        s = f4fma(wx * omy, sb[((r0 + x1) << 2) + j], s);
        s = f4fma(omx * wy, sb[((r1 + x0) << 2) + j], s);
        s = f4fma(wx * wy, sb[((r1 + x1) << 2) + j], s);
        acc = f4fma(tp.z, s, acc);
        den += tp.z;
    }
    return f4scale(1.0f / den, acc);
}

// ---------------- K2: fine deform  (n1 -> a1) ----------------
__global__ void __launch_bounds__(128)
k2_fine(const float* __restrict__ dww, const float* __restrict__ dwb,
        const float* __restrict__ pww, const float* __restrict__ pwb) {
    __shared__ float s_dww[144], s_dwb[16], s_pwb[75];
    __shared__ float4 s_pw4[75 * 5];
    __shared__ float4 s_tap[32][25];
    int tid = threadIdx.x;
    ldblk(s_dww, dww, 144, tid);
    ldblk(s_dwb, dwb, 16, tid);
    ldblk(s_pwb, pwb, 75, tid);
    ldpad((float*)s_pw4, pww, 75, tid);
    __syncthreads();

    int t = blockIdx.x * blockDim.x + tid;
    int p = t >> 2, j = t & 3;
    int lane = tid & 31;
    int g = tid >> 2;
    int b = p >> 16, y = (p >> 8) & 255, x = p & 255;
    const float4* sb = g4_n1 + ((size_t)b << 18);
    g4_a1[(size_t)p * 4 + j] =
        deform_core4(sb, y, x, lane, j, s_dww, s_dwb, s_pw4, s_pwb, 1.0f, 4.0f, &s_tap[g][0]);
}

// ---------------- K3: coarse deform + rmsnorm + gate + proj_out + sigma ----------------
__global__ void __launch_bounds__(128)
k3_coarse_tail(const float* __restrict__ dww, const float* __restrict__ dwb,
               const float* __restrict__ pww, const float* __restrict__ pwb,
               const float* __restrict__ n2w,
               const float* __restrict__ gate_w, const float* __restrict__ gate_b,
               const float* __restrict__ pout_w, const float* __restrict__ pout_b,
               const float* __restrict__ sig_w, const float* __restrict__ sig_b) {
    __shared__ float s_dww[144], s_dwb[16], s_pwb[75], s_n2w[16], s_sigb[3];
    __shared__ float4 s_pw4[75 * 5];
    __shared__ float4 s_gT4[16 * 5], s_pT4[16 * 5];   // transposed, padded
    __shared__ float4 s_gb4[4], s_pb4[4], s_sig4[12];
    __shared__ float4 s_tap[32][25];
    int tid = threadIdx.x;
    ldblk(s_dww, dww, 144, tid);
    ldblk(s_dwb, dwb, 16, tid);
    ldblk(s_pwb, pwb, 75, tid);
    ldpad((float*)s_pw4, pww, 75, tid);
    ldtpad((float*)s_gT4, gate_w, tid);
    ldtpad((float*)s_pT4, pout_w, tid);
    ldblk((float*)s_gb4, gate_b, 16, tid);
    ldblk((float*)s_pb4, pout_b, 16, tid);
    ldblk((float*)s_sig4, sig_w, 48, tid);
    ldblk(s_n2w, n2w, 16, tid);
    ldblk(s_sigb, sig_b, 3, tid);
    __syncthreads();

    int t = blockIdx.x * blockDim.x + tid;
    int p = t >> 2, j = t & 3;
    int lane = tid & 31;
    int g = tid >> 2;
    int b = p >> 16, y = (p >> 8) & 255, x = p & 255;
    const int c0 = 4 * j;
    const float4* sb = g4_a1 + ((size_t)b << 18);

    float4 av = deform_core4(sb, y, x, lane, j, s_dww, s_dwb, s_pw4, s_pwb,
                             3.0f, 6.0f, &s_tap[g][0]);

    // rmsnorm(a2, norm2)
    float ssp = av.x * av.x + av.y * av.y + av.z * av.z + av.w * av.w;
    float ss = rsum4(ssp);
    float inv = 1.0f / (sqrtf(ss) * 0.25f + EPSF);
    float4 tv = make_float4(av.x * inv * s_n2w[c0], av.y * inv * s_n2w[c0 + 1],
                            av.z * inv * s_n2w[c0 + 2], av.w * inv * s_n2w[c0 + 3]);

    float4 tf[4];
    bcast16v(tv, lane, tf);

    // gate conv via transposed weights: lane accumulates its 4 outputs as float4
    float4 a3 = s_gb4[j];
#pragma unroll
    for (int r = 0; r < 4; r++) {
        a3 = f4fma(tf[r].x, s_gT4[(4 * r + 0) * 5 + j], a3);
        a3 = f4fma(tf[r].y, s_gT4[(4 * r + 1) * 5 + j], a3);
        a3 = f4fma(tf[r].z, s_gT4[(4 * r + 2) * 5 + j], a3);
        a3 = f4fma(tf[r].w, s_gT4[(4 * r + 3) * 5 + j], a3);
    }
    float4 f0v = g4_feat0[(size_t)p * 4 + j];
    float4 gv = make_float4(f0v.x * a3.x, f0v.y * a3.y, f0v.z * a3.z, f0v.w * a3.w);

    float4 gf[4];
    bcast16v(gv, lane, gf);

    // feat = proj_out(g) + b + shortcut
    float4 fv = f4add(s_pb4[j], g4_short[(size_t)p * 4 + j]);
#pragma unroll
    for (int r = 0; r < 4; r++) {
        fv = f4fma(gf[r].x, s_pT4[(4 * r + 0) * 5 + j], fv);
        fv = f4fma(gf[r].y, s_pT4[(4 * r + 1) * 5 + j], fv);
        fv = f4fma(gf[r].z, s_pT4[(4 * r + 2) * 5 + j], fv);
        fv = f4fma(gf[r].w, s_pT4[(4 * r + 3) * 5 + j], fv);
    }
    g4_feat[(size_t)p * 4 + j] = fv;

    // sigma head
    float sg[3];
#pragma unroll
    for (int r = 0; r < 3; r++) {
        float zp = dot44(fv, s_sig4[r * 4 + j]);
        float z = rsum4(zp) + s_sigb[r];
        float sp = fmaxf(z, 0.0f) + log1pf(expf(-fabsf(z)));
        sg[r] = fminf(sp, 6.0f) + EPSF;
    }
    if (j == 0) g_sig[p] = make_float4(sg[0], sg[1], sg[2], 0.0f);
}

// ---------------- K4: joint bilateral ----------------
__global__ void __launch_bounds__(128)
k4_bilateral(const float* __restrict__ xin,
             const float* __restrict__ offw, const float* __restrict__ offb,
             float* __restrict__ out) {
    __shared__ float4 s_ow4[50 * 5];
    __shared__ float s_ob[50];
    __shared__ float4 s_tap[32][25];
    int tid = threadIdx.x;
    ldpad((float*)s_ow4, offw, 50, tid);
    ldblk(s_ob, offb, 50, tid);
    __syncthreads();

    int t = blockIdx.x * blockDim.x + tid;
    int p = t >> 2, j = t & 3;
    int lane = tid & 31;
    int g = tid >> 2;
    int b = p >> 16, y = (p >> 8) & 255, x = p & 255;

    float4 fv = g4_feat[(size_t)p * 4 + j];
    float4 fvv[4];
    bcast16v(fv, lane, fvv);

    float4 s4 = g_sig[p];
    float axc = 0.5f / (s4.x * s4.x);
    float ayc = 0.5f / (s4.y * s4.y);
    float arc = 0.5f / (s4.z * s4.z);

    const float* plane = xin + (size_t)b * 4 * HW;
    const float4* fb = g4_feat + ((size_t)b << 18);
    float4* tap_s = &s_tap[g][0];

    // phase 1: lane j owns k = j, j+4, ...
    for (int k = j; k < 25; k += 4) {
        const float4* wx4 = s_ow4 + (2 * k) * 5;
        const float4* wy4 = s_ow4 + (2 * k + 1) * 5;
        float px = s_ob[2 * k], py = s_ob[2 * k + 1];
#pragma unroll
        for (int q = 0; q < 4; q++) {
            px += dot44(fvv[q], wx4[q]);
            py += dot44(fvv[q], wy4[q]);
        }
        float dx = (float)((k % 5) - 2) + tanh_p(px) * 5.0f;
        float dy = (float)((k / 5) - 2) + tanh_p(py) * 5.0f;
        float spat = dx * dx * axc + dy * dy * ayc;
        tap_s[k] = make_float4(reflectf((float)x + dx), reflectf((float)y + dy), spat, 0.0f);
    }
    __syncwarp();

    // phase 2
    float num = 0.0f, den = 0.0f;
#pragma unroll 1
    for (int k = 0; k < 25; k++) {
        float4 tp = tap_s[k];
        float fx = floorf(tp.x), fy = floorf(tp.y);
        float wx = tp.x - fx, wy = tp.y - fy;
        int x0 = (int)fx, y0 = (int)fy;
        int x1 = min(x0 + 1, 255), y1 = min(y0 + 1, 255);
        int r0 = y0 << 8, r1 = y1 << 8;
        int i00 = r0 + x0, i01 = r0 + x1, i10 = r1 + x0, i11 = r1 + x1;
        float omx = 1.0f - wx, omy = 1.0f - wy;
        float w00 = omx * omy, w01 = wx * omy, w10 = omx * wy, w11 = wx * wy;

        // feat gather: this lane's chunk from all 4 corners
        float4 s = f4scale(w00, fb[(i00 << 2) + j]);
        s = f4fma(w01, fb[(i01 << 2) + j], s);
        s = f4fma(w10, fb[(i10 << 2) + j], s);
        s = f4fma(w11, fb[(i11 << 2) + j], s);
        float ddx = fv.x - s.x, ddy = fv.y - s.y, ddz = fv.z - s.z, ddw = fv.w - s.w;
        float fdp = ddx * ddx + ddy * ddy + ddz * ddz + ddw * ddw;

        // patch partial: lane j loads its corner only
        int ci = (j & 2) ? ((j & 1) ? i11 : i10) : ((j & 1) ? i01 : i00);
        float cw = (j & 2) ? ((j & 1) ? w11 : w10) : ((j & 1) ? w01 : w00);
        float pp = cw * plane[ci];

        float fd = rsum4(fdp);
        float patch = rsum4(pp);

        float w = __expf(-tp.z - fd * arc);
        num = fmaf(patch, w, num);
        den += w;
    }
    if (j == 0) out[p] = num / (den + 1e-8f);
}

// ---------------- launch ----------------
extern "C" void kernel_launch(void* const* d_in, const int* in_sizes, int n_in,
                              void* d_out, int out_size) {
    const float* x = (const float*)d_in[0];
    const int TB = 128;
    const int NB4 = (NPIX * 4) / TB;   // 4 lanes per pixel

    k1_proj<<<NB4, TB>>>(x, (const float*)d_in[1], (const float*)d_in[2],
                         (const float*)d_in[3], (const float*)d_in[4],
                         (const float*)d_in[5]);
    k2_fine<<<NB4, TB>>>((const float*)d_in[6], (const float*)d_in[7],
                         (const float*)d_in[8], (const float*)d_in[9]);
    k3_coarse_tail<<<NB4, TB>>>((const float*)d_in[10], (const float*)d_in[11],
                                (const float*)d_in[12], (const float*)d_in[13],
                                (const float*)d_in[14],
                                (const float*)d_in[15], (const float*)d_in[16],
                                (const float*)d_in[17], (const float*)d_in[18],
                                (const float*)d_in[19], (const float*)d_in[20]);
    k4_bilateral<<<NB4, TB>>>(x, (const float*)d_in[21], (const float*)d_in[22],
                              (float*)d_out);
}